// round 2
// baseline (speedup 1.0000x reference)
#include <cuda_runtime.h>
#include <cstdint>

#define M_TILE   64
#define H        256
#define H3       768
#define LATENT   128
#define T_STEPS  180
#define HPAD     260          // h row pitch in floats (16B-aligned, conflict-benign)
#define NCTA     128
#define NTHR     256
#define OFFJ     (16*H)       // float offset between a thread's consecutive W rows

// packed fp32x2 FMA (sm_103a FFMA2)
#define FMA2(acc, a, b) asm("fma.rn.f32x2 %0, %1, %2, %0;" : "+l"(acc) : "l"(a), "l"(b))

__device__ __forceinline__ float lo32(unsigned long long v){ return __uint_as_float((unsigned)(v & 0xffffffffull)); }
__device__ __forceinline__ float hi32(unsigned long long v){ return __uint_as_float((unsigned)(v >> 32)); }
__device__ __forceinline__ ulonglong2 ld2(const float* p){ return *reinterpret_cast<const ulonglong2*>(p); }

__device__ __forceinline__ float sigmoidf_(float x){ return 1.0f/(1.0f + __expf(-x)); }
__device__ __forceinline__ float tanhf_(float x){ return 2.0f/(1.0f + __expf(-2.0f*x)) - 1.0f; }

__global__ __launch_bounds__(NTHR, 1)
void gru_decoder_kernel(const float* __restrict__ z,
                        const float* __restrict__ fc_w,
                        const float* __restrict__ fc_b,
                        const float* __restrict__ b_ih,
                        const float* __restrict__ w_hh,
                        const float* __restrict__ b_hh,
                        const float* __restrict__ out_w,
                        const float* __restrict__ out_b,
                        float* __restrict__ out)
{
    extern __shared__ float smem[];
    float* hbufA = smem;                    // [64][HPAD]
    float* hbufB = smem + M_TILE*HPAD;      // [64][HPAD]
    float* bsr   = smem + 2*M_TILE*HPAD;    // [256] b_ih_r + b_hh_r
    float* bsz   = bsr + H;                 // [256] b_ih_z + b_hh_z
    float* bin   = bsz + H;                 // [256] b_ih_n
    float* bhn   = bin + H;                 // [256] b_hh_n
    float* ows   = bhn + H;                 // [2][256]
    float* obs   = ows + 2*H;               // [2]

    const int tid = threadIdx.x;
    const int mg  = tid & 15;               // 16 m-groups, rows mg + 16*mm
    const int jg  = tid >> 4;               // 16 j-groups, cols jb*64 + jg + 16*jj
    const int mbase = blockIdx.x * M_TILE;

    // ---- preload biases / output weights into smem ----
    for (int i = tid; i < H; i += NTHR) {
        bsr[i] = b_ih[i]       + b_hh[i];
        bsz[i] = b_ih[H + i]   + b_hh[H + i];
        bin[i] = b_ih[2*H + i];
        bhn[i] = b_hh[2*H + i];
        ows[i]     = out_w[i];
        ows[H + i] = out_w[H + i];
    }
    if (tid < 2) obs[tid] = out_b[tid];

    // ---- stage z tile into hbufB (coalesced) ----
    for (int i = tid; i < M_TILE * (LATENT/4); i += NTHR) {
        int m  = i / (LATENT/4);
        int k4 = i % (LATENT/4);
        reinterpret_cast<float4*>(hbufB + m*HPAD)[k4] =
            reinterpret_cast<const float4*>(z + (size_t)(mbase+m)*LATENT)[k4];
    }
    __syncthreads();

    // ---- h0 = tanh(z @ fc_w^T + fc_b) into hbufA ----
    for (int jb = 0; jb < 4; jb++) {
        float acc[4][4];
        #pragma unroll
        for (int a=0;a<4;a++) { acc[a][0]=0.f; acc[a][1]=0.f; acc[a][2]=0.f; acc[a][3]=0.f; }
        const float* wb = fc_w + (size_t)(jb*64 + jg) * LATENT;
        for (int k4 = 0; k4 < LATENT/4; k4++) {
            float4 zv[4], wv[4];
            #pragma unroll
            for (int mm=0;mm<4;mm++)
                zv[mm] = *reinterpret_cast<const float4*>(hbufB + (mg+16*mm)*HPAD + 4*k4);
            #pragma unroll
            for (int jj=0;jj<4;jj++)
                wv[jj] = *reinterpret_cast<const float4*>(wb + jj*(16*LATENT) + 4*k4);
            #pragma unroll
            for (int mm=0;mm<4;mm++)
                #pragma unroll
                for (int jj=0;jj<4;jj++)
                    acc[mm][jj] += zv[mm].x*wv[jj].x + zv[mm].y*wv[jj].y
                                 + zv[mm].z*wv[jj].z + zv[mm].w*wv[jj].w;
        }
        #pragma unroll
        for (int jj=0;jj<4;jj++) {
            int j = jb*64 + jg + 16*jj;
            float fb = fc_b[j];
            #pragma unroll
            for (int mm=0;mm<4;mm++)
                hbufA[(mg+16*mm)*HPAD + j] = tanhf_(acc[mm][jj] + fb);
        }
    }
    __syncthreads();

    float* hc = hbufA;   // current h
    float* hn = hbufB;   // next h

    for (int t = 0; t < T_STEPS; t++) {
        for (int jb = 0; jb < 4; jb++) {
            const int j0 = jb*64 + jg;
            const float* wr_base = w_hh + (size_t)j0 * H;              // r-gate rows
            const float* wz_base = wr_base + (size_t)H * H;            // z-gate rows
            const float* hrow    = hc + mg*HPAD;

            // ================= phase A: r and z gates =================
            unsigned long long ar[4][4], az[4][4];
            #pragma unroll
            for (int mm=0;mm<4;mm++)
                #pragma unroll
                for (int jj=0;jj<4;jj++) { ar[mm][jj]=0ull; az[mm][jj]=0ull; }

            ulonglong2 wr0[4], wr1[4], wz0[4], wz1[4];
            #pragma unroll
            for (int jj=0;jj<4;jj++) {
                wr0[jj] = ld2(wr_base + jj*OFFJ);
                wz0[jj] = ld2(wz_base + jj*OFFJ);
            }
            for (int k4 = 0; k4 < 64; k4 += 2) {
                // ---- half 1: compute k4 from buf0, prefetch k4+1 into buf1 ----
                #pragma unroll
                for (int jj=0;jj<4;jj++) {
                    wr1[jj] = ld2(wr_base + jj*OFFJ + 4*(k4+1));
                    wz1[jj] = ld2(wz_base + jj*OFFJ + 4*(k4+1));
                }
                {
                    ulonglong2 hv[4];
                    #pragma unroll
                    for (int mm=0;mm<4;mm++) hv[mm] = ld2(hrow + mm*(16*HPAD) + 4*k4);
                    #pragma unroll
                    for (int mm=0;mm<4;mm++)
                        #pragma unroll
                        for (int jj=0;jj<4;jj++) {
                            FMA2(ar[mm][jj], hv[mm].x, wr0[jj].x);
                            FMA2(ar[mm][jj], hv[mm].y, wr0[jj].y);
                            FMA2(az[mm][jj], hv[mm].x, wz0[jj].x);
                            FMA2(az[mm][jj], hv[mm].y, wz0[jj].y);
                        }
                }
                // ---- half 2: compute k4+1 from buf1, prefetch k4+2 into buf0 ----
                int k2 = (k4+2 < 64) ? (k4+2) : 63;
                #pragma unroll
                for (int jj=0;jj<4;jj++) {
                    wr0[jj] = ld2(wr_base + jj*OFFJ + 4*k2);
                    wz0[jj] = ld2(wz_base + jj*OFFJ + 4*k2);
                }
                {
                    ulonglong2 hv[4];
                    #pragma unroll
                    for (int mm=0;mm<4;mm++) hv[mm] = ld2(hrow + mm*(16*HPAD) + 4*(k4+1));
                    #pragma unroll
                    for (int mm=0;mm<4;mm++)
                        #pragma unroll
                        for (int jj=0;jj<4;jj++) {
                            FMA2(ar[mm][jj], hv[mm].x, wr1[jj].x);
                            FMA2(ar[mm][jj], hv[mm].y, wr1[jj].y);
                            FMA2(az[mm][jj], hv[mm].x, wz1[jj].x);
                            FMA2(az[mm][jj], hv[mm].y, wz1[jj].y);
                        }
                }
            }

            // ---- gates r, z ----
            float r_[4][4], zg_[4][4];
            #pragma unroll
            for (int jj=0;jj<4;jj++) {
                int j = j0 + 16*jj;
                float br = bsr[j], bz = bsz[j];
                #pragma unroll
                for (int mm=0;mm<4;mm++) {
                    r_[mm][jj]  = sigmoidf_(lo32(ar[mm][jj]) + hi32(ar[mm][jj]) + br);
                    zg_[mm][jj] = sigmoidf_(lo32(az[mm][jj]) + hi32(az[mm][jj]) + bz);
                }
            }

            // ================= phase B: n gate =================
            const float* wn_base = w_hh + (size_t)(2*H + j0) * H;
            unsigned long long an[4][4];
            #pragma unroll
            for (int mm=0;mm<4;mm++)
                #pragma unroll
                for (int jj=0;jj<4;jj++) an[mm][jj]=0ull;

            ulonglong2 wn0[4], wn1[4];
            #pragma unroll
            for (int jj=0;jj<4;jj++) wn0[jj] = ld2(wn_base + jj*OFFJ);

            for (int k4 = 0; k4 < 64; k4 += 2) {
                #pragma unroll
                for (int jj=0;jj<4;jj++) wn1[jj] = ld2(wn_base + jj*OFFJ + 4*(k4+1));
                {
                    ulonglong2 hv[4];
                    #pragma unroll
                    for (int mm=0;mm<4;mm++) hv[mm] = ld2(hrow + mm*(16*HPAD) + 4*k4);
                    #pragma unroll
                    for (int mm=0;mm<4;mm++)
                        #pragma unroll
                        for (int jj=0;jj<4;jj++) {
                            FMA2(an[mm][jj], hv[mm].x, wn0[jj].x);
                            FMA2(an[mm][jj], hv[mm].y, wn0[jj].y);
                        }
                }
                int k2 = (k4+2 < 64) ? (k4+2) : 63;
                #pragma unroll
                for (int jj=0;jj<4;jj++) wn0[jj] = ld2(wn_base + jj*OFFJ + 4*k2);
                {
                    ulonglong2 hv[4];
                    #pragma unroll
                    for (int mm=0;mm<4;mm++) hv[mm] = ld2(hrow + mm*(16*HPAD) + 4*(k4+1));
                    #pragma unroll
                    for (int mm=0;mm<4;mm++)
                        #pragma unroll
                        for (int jj=0;jj<4;jj++) {
                            FMA2(an[mm][jj], hv[mm].x, wn1[jj].x);
                            FMA2(an[mm][jj], hv[mm].y, wn1[jj].y);
                        }
                }
            }

            // ---- n gate + h update (write to hn) ----
            #pragma unroll
            for (int jj=0;jj<4;jj++) {
                int j = j0 + 16*jj;
                float bi = bin[j], bh = bhn[j];
                #pragma unroll
                for (int mm=0;mm<4;mm++) {
                    float ghn = lo32(an[mm][jj]) + hi32(an[mm][jj]);
                    float nv  = tanhf_(bi + r_[mm][jj] * (ghn + bh));
                    float hold = hc[(mg+16*mm)*HPAD + j];
                    hn[(mg+16*mm)*HPAD + j] = nv + zg_[mm][jj] * (hold - nv);
                }
            }
        } // jb

        __syncthreads();

        // ---- fused output projection: out[b,t,:] = h_new @ out_w^T + out_b ----
        if (tid < 128) {
            int m = tid >> 1, o = tid & 1;
            float s0 = obs[o], s1 = 0.f;
            const float4* hp = reinterpret_cast<const float4*>(hn + m*HPAD);
            const float4* wp = reinterpret_cast<const float4*>(ows + o*H);
            #pragma unroll 8
            for (int k4 = 0; k4 < 64; k4 += 2) {
                float4 a0 = hp[k4],   b0 = wp[k4];
                float4 a1 = hp[k4+1], b1 = wp[k4+1];
                s0 += a0.x*b0.x + a0.y*b0.y + a0.z*b0.z + a0.w*b0.w;
                s1 += a1.x*b1.x + a1.y*b1.y + a1.z*b1.z + a1.w*b1.w;
            }
            out[((size_t)(mbase+m)*T_STEPS + t)*2 + o] = s0 + s1;
        }

        // swap buffers (no extra sync needed: per-thread program order +
        // the single barrier above covers all cross-buffer hazards)
        float* tmp = hc; hc = hn; hn = tmp;
    }
}

extern "C" void kernel_launch(void* const* d_in, const int* in_sizes, int n_in,
                              void* d_out, int out_size)
{
    (void)in_sizes; (void)n_in; (void)out_size;
    const float* z     = (const float*)d_in[0];
    const float* fc_w  = (const float*)d_in[1];
    const float* fc_b  = (const float*)d_in[2];
    /* d_in[3] = w_ih: unused — GRU input is all-zeros, gi reduces to b_ih */
    const float* b_ih  = (const float*)d_in[4];
    const float* w_hh  = (const float*)d_in[5];
    const float* b_hh  = (const float*)d_in[6];
    const float* out_w = (const float*)d_in[7];
    const float* out_b = (const float*)d_in[8];

    const size_t smem_bytes =
        (2*M_TILE*HPAD + 4*H + 2*H + 2) * sizeof(float);   // ~139.3 KB

    cudaFuncSetAttribute(gru_decoder_kernel,
                         cudaFuncAttributeMaxDynamicSharedMemorySize,
                         (int)smem_bytes);

    gru_decoder_kernel<<<NCTA, NTHR, smem_bytes>>>(
        z, fc_w, fc_b, b_ih, w_hh, b_hh, out_w, out_b, (float*)d_out);
}

// round 4
// speedup vs baseline: 1.0014x; 1.0014x over previous
#include <cuda_runtime.h>
#include <cstdint>

#define M_TILE   64
#define H        256
#define H3       768
#define LATENT   128
#define T_STEPS  180
#define HPAD     260          // h row pitch in floats (16B-aligned, conflict-benign)
#define NCTA     128
#define NTHR     256
#define OFFJ     (16*H)       // float offset between a thread's consecutive W rows

// packed fp32x2 FMA (sm_103a FFMA2)
#define FMA2(acc, a, b) asm("fma.rn.f32x2 %0, %1, %2, %0;" : "+l"(acc) : "l"(a), "l"(b))

__device__ __forceinline__ float lo32(unsigned long long v){ return __uint_as_float((unsigned)(v & 0xffffffffull)); }
__device__ __forceinline__ float hi32(unsigned long long v){ return __uint_as_float((unsigned)(v >> 32)); }
__device__ __forceinline__ ulonglong2 ld2(const float* p){ return *reinterpret_cast<const ulonglong2*>(p); }

__device__ __forceinline__ float sigmoidf_(float x){ return 1.0f/(1.0f + __expf(-x)); }
__device__ __forceinline__ float tanhf_(float x){ return 2.0f/(1.0f + __expf(-2.0f*x)) - 1.0f; }

__global__ __launch_bounds__(NTHR, 1)
void gru_decoder_kernel(const float* __restrict__ z,
                        const float* __restrict__ fc_w,
                        const float* __restrict__ fc_b,
                        const float* __restrict__ b_ih,
                        const float* __restrict__ w_hh,
                        const float* __restrict__ b_hh,
                        const float* __restrict__ out_w,
                        const float* __restrict__ out_b,
                        float* __restrict__ out)
{
    extern __shared__ float smem[];
    float* hbufA = smem;                    // [64][HPAD]
    float* hbufB = smem + M_TILE*HPAD;      // [64][HPAD]
    float* bsr   = smem + 2*M_TILE*HPAD;    // [256] b_ih_r + b_hh_r
    float* bsz   = bsr + H;                 // [256] b_ih_z + b_hh_z
    float* bin   = bsz + H;                 // [256] b_ih_n
    float* bhn   = bin + H;                 // [256] b_hh_n
    float* ows   = bhn + H;                 // [2][256]
    float* obs   = ows + 2*H;               // [2]

    const int tid = threadIdx.x;
    const int mg  = tid & 15;               // 16 m-groups, rows mg + 16*mm
    const int jg  = tid >> 4;               // 16 j-groups, cols jb*64 + jg + 16*jj
    const int mbase = blockIdx.x * M_TILE;

    // ---- preload biases / output weights into smem ----
    for (int i = tid; i < H; i += NTHR) {
        bsr[i] = b_ih[i]       + b_hh[i];
        bsz[i] = b_ih[H + i]   + b_hh[H + i];
        bin[i] = b_ih[2*H + i];
        bhn[i] = b_hh[2*H + i];
        ows[i]     = out_w[i];
        ows[H + i] = out_w[H + i];
    }
    if (tid < 2) obs[tid] = out_b[tid];

    // ---- stage z tile into hbufB (coalesced) ----
    for (int i = tid; i < M_TILE * (LATENT/4); i += NTHR) {
        int m  = i / (LATENT/4);
        int k4 = i % (LATENT/4);
        reinterpret_cast<float4*>(hbufB + m*HPAD)[k4] =
            reinterpret_cast<const float4*>(z + (size_t)(mbase+m)*LATENT)[k4];
    }
    __syncthreads();

    // ---- h0 = tanh(z @ fc_w^T + fc_b) into hbufA ----
    for (int jb = 0; jb < 4; jb++) {
        float acc[4][4];
        #pragma unroll
        for (int a=0;a<4;a++) { acc[a][0]=0.f; acc[a][1]=0.f; acc[a][2]=0.f; acc[a][3]=0.f; }
        const float* wb = fc_w + (size_t)(jb*64 + jg) * LATENT;
        for (int k4 = 0; k4 < LATENT/4; k4++) {
            float4 zv[4], wv[4];
            #pragma unroll
            for (int mm=0;mm<4;mm++)
                zv[mm] = *reinterpret_cast<const float4*>(hbufB + (mg+16*mm)*HPAD + 4*k4);
            #pragma unroll
            for (int jj=0;jj<4;jj++)
                wv[jj] = *reinterpret_cast<const float4*>(wb + jj*(16*LATENT) + 4*k4);
            #pragma unroll
            for (int mm=0;mm<4;mm++)
                #pragma unroll
                for (int jj=0;jj<4;jj++)
                    acc[mm][jj] += zv[mm].x*wv[jj].x + zv[mm].y*wv[jj].y
                                 + zv[mm].z*wv[jj].z + zv[mm].w*wv[jj].w;
        }
        #pragma unroll
        for (int jj=0;jj<4;jj++) {
            int j = jb*64 + jg + 16*jj;
            float fb = fc_b[j];
            #pragma unroll
            for (int mm=0;mm<4;mm++)
                hbufA[(mg+16*mm)*HPAD + j] = tanhf_(acc[mm][jj] + fb);
        }
    }
    __syncthreads();

    float* hc = hbufA;   // current h
    float* hn = hbufB;   // next h

    for (int t = 0; t < T_STEPS; t++) {
        for (int jb = 0; jb < 4; jb++) {
            const int j0 = jb*64 + jg;
            const float* wr_base = w_hh + (size_t)j0 * H;              // r-gate rows
            const float* wz_base = wr_base + (size_t)H * H;            // z-gate rows
            const float* hrow    = hc + mg*HPAD;

            // ================= phase A: r and z gates =================
            unsigned long long ar[4][4], az[4][4];
            #pragma unroll
            for (int mm=0;mm<4;mm++)
                #pragma unroll
                for (int jj=0;jj<4;jj++) { ar[mm][jj]=0ull; az[mm][jj]=0ull; }

            ulonglong2 wr0[4], wr1[4], wz0[4], wz1[4];
            #pragma unroll
            for (int jj=0;jj<4;jj++) {
                wr0[jj] = ld2(wr_base + jj*OFFJ);
                wz0[jj] = ld2(wz_base + jj*OFFJ);
            }
            for (int k4 = 0; k4 < 64; k4 += 2) {
                // ---- half 1: compute k4 from buf0, prefetch k4+1 into buf1 ----
                #pragma unroll
                for (int jj=0;jj<4;jj++) {
                    wr1[jj] = ld2(wr_base + jj*OFFJ + 4*(k4+1));
                    wz1[jj] = ld2(wz_base + jj*OFFJ + 4*(k4+1));
                }
                {
                    ulonglong2 hv[4];
                    #pragma unroll
                    for (int mm=0;mm<4;mm++) hv[mm] = ld2(hrow + mm*(16*HPAD) + 4*k4);
                    #pragma unroll
                    for (int mm=0;mm<4;mm++)
                        #pragma unroll
                        for (int jj=0;jj<4;jj++) {
                            FMA2(ar[mm][jj], hv[mm].x, wr0[jj].x);
                            FMA2(ar[mm][jj], hv[mm].y, wr0[jj].y);
                            FMA2(az[mm][jj], hv[mm].x, wz0[jj].x);
                            FMA2(az[mm][jj], hv[mm].y, wz0[jj].y);
                        }
                }
                // ---- half 2: compute k4+1 from buf1, prefetch k4+2 into buf0 ----
                int k2 = (k4+2 < 64) ? (k4+2) : 63;
                #pragma unroll
                for (int jj=0;jj<4;jj++) {
                    wr0[jj] = ld2(wr_base + jj*OFFJ + 4*k2);
                    wz0[jj] = ld2(wz_base + jj*OFFJ + 4*k2);
                }
                {
                    ulonglong2 hv[4];
                    #pragma unroll
                    for (int mm=0;mm<4;mm++) hv[mm] = ld2(hrow + mm*(16*HPAD) + 4*(k4+1));
                    #pragma unroll
                    for (int mm=0;mm<4;mm++)
                        #pragma unroll
                        for (int jj=0;jj<4;jj++) {
                            FMA2(ar[mm][jj], hv[mm].x, wr1[jj].x);
                            FMA2(ar[mm][jj], hv[mm].y, wr1[jj].y);
                            FMA2(az[mm][jj], hv[mm].x, wz1[jj].x);
                            FMA2(az[mm][jj], hv[mm].y, wz1[jj].y);
                        }
                }
            }

            // ---- gates r, z ----
            float r_[4][4], zg_[4][4];
            #pragma unroll
            for (int jj=0;jj<4;jj++) {
                int j = j0 + 16*jj;
                float br = bsr[j], bz = bsz[j];
                #pragma unroll
                for (int mm=0;mm<4;mm++) {
                    r_[mm][jj]  = sigmoidf_(lo32(ar[mm][jj]) + hi32(ar[mm][jj]) + br);
                    zg_[mm][jj] = sigmoidf_(lo32(az[mm][jj]) + hi32(az[mm][jj]) + bz);
                }
            }

            // ================= phase B: n gate =================
            const float* wn_base = w_hh + (size_t)(2*H + j0) * H;
            unsigned long long an[4][4];
            #pragma unroll
            for (int mm=0;mm<4;mm++)
                #pragma unroll
                for (int jj=0;jj<4;jj++) an[mm][jj]=0ull;

            ulonglong2 wn0[4], wn1[4];
            #pragma unroll
            for (int jj=0;jj<4;jj++) wn0[jj] = ld2(wn_base + jj*OFFJ);

            for (int k4 = 0; k4 < 64; k4 += 2) {
                #pragma unroll
                for (int jj=0;jj<4;jj++) wn1[jj] = ld2(wn_base + jj*OFFJ + 4*(k4+1));
                {
                    ulonglong2 hv[4];
                    #pragma unroll
                    for (int mm=0;mm<4;mm++) hv[mm] = ld2(hrow + mm*(16*HPAD) + 4*k4);
                    #pragma unroll
                    for (int mm=0;mm<4;mm++)
                        #pragma unroll
                        for (int jj=0;jj<4;jj++) {
                            FMA2(an[mm][jj], hv[mm].x, wn0[jj].x);
                            FMA2(an[mm][jj], hv[mm].y, wn0[jj].y);
                        }
                }
                int k2 = (k4+2 < 64) ? (k4+2) : 63;
                #pragma unroll
                for (int jj=0;jj<4;jj++) wn0[jj] = ld2(wn_base + jj*OFFJ + 4*k2);
                {
                    ulonglong2 hv[4];
                    #pragma unroll
                    for (int mm=0;mm<4;mm++) hv[mm] = ld2(hrow + mm*(16*HPAD) + 4*(k4+1));
                    #pragma unroll
                    for (int mm=0;mm<4;mm++)
                        #pragma unroll
                        for (int jj=0;jj<4;jj++) {
                            FMA2(an[mm][jj], hv[mm].x, wn1[jj].x);
                            FMA2(an[mm][jj], hv[mm].y, wn1[jj].y);
                        }
                }
            }

            // ---- n gate + h update (write to hn) ----
            #pragma unroll
            for (int jj=0;jj<4;jj++) {
                int j = j0 + 16*jj;
                float bi = bin[j], bh = bhn[j];
                #pragma unroll
                for (int mm=0;mm<4;mm++) {
                    float ghn = lo32(an[mm][jj]) + hi32(an[mm][jj]);
                    float nv  = tanhf_(bi + r_[mm][jj] * (ghn + bh));
                    float hold = hc[(mg+16*mm)*HPAD + j];
                    hn[(mg+16*mm)*HPAD + j] = nv + zg_[mm][jj] * (hold - nv);
                }
            }
        } // jb

        __syncthreads();

        // ---- fused output projection: out[b,t,:] = h_new @ out_w^T + out_b ----
        if (tid < 128) {
            int m = tid >> 1, o = tid & 1;
            float s0 = obs[o], s1 = 0.f;
            const float4* hp = reinterpret_cast<const float4*>(hn + m*HPAD);
            const float4* wp = reinterpret_cast<const float4*>(ows + o*H);
            #pragma unroll 8
            for (int k4 = 0; k4 < 64; k4 += 2) {
                float4 a0 = hp[k4],   b0 = wp[k4];
                float4 a1 = hp[k4+1], b1 = wp[k4+1];
                s0 += a0.x*b0.x + a0.y*b0.y + a0.z*b0.z + a0.w*b0.w;
                s1 += a1.x*b1.x + a1.y*b1.y + a1.z*b1.z + a1.w*b1.w;
            }
            out[((size_t)(mbase+m)*T_STEPS + t)*2 + o] = s0 + s1;
        }

        // swap buffers (no extra sync needed: per-thread program order +
        // the single barrier above covers all cross-buffer hazards)
        float* tmp = hc; hc = hn; hn = tmp;
    }
}

extern "C" void kernel_launch(void* const* d_in, const int* in_sizes, int n_in,
                              void* d_out, int out_size)
{
    (void)in_sizes; (void)n_in; (void)out_size;
    const float* z     = (const float*)d_in[0];
    const float* fc_w  = (const float*)d_in[1];
    const float* fc_b  = (const float*)d_in[2];
    /* d_in[3] = w_ih: unused — GRU input is all-zeros, gi reduces to b_ih */
    const float* b_ih  = (const float*)d_in[4];
    const float* w_hh  = (const float*)d_in[5];
    const float* b_hh  = (const float*)d_in[6];
    const float* out_w = (const float*)d_in[7];
    const float* out_b = (const float*)d_in[8];

    const size_t smem_bytes =
        (2*M_TILE*HPAD + 4*H + 2*H + 2) * sizeof(float);   // ~139.3 KB

    cudaFuncSetAttribute(gru_decoder_kernel,
                         cudaFuncAttributeMaxDynamicSharedMemorySize,
                         (int)smem_bytes);

    gru_decoder_kernel<<<NCTA, NTHR, smem_bytes>>>(
        z, fc_w, fc_b, b_ih, w_hh, b_hh, out_w, out_b, (float*)d_out);
}